// round 1
// baseline (speedup 1.0000x reference)
#include <cuda_runtime.h>

#define NN 100000
#define EE 1600000
#define HH 4
#define CC 32
#define DD 128
#define GG 64
#define NEG 0.2f
#define NB1 ((NN + 1023) / 1024)

// ---------------- device scratch (no runtime allocation allowed) ----------------
__device__ float g_hA[(size_t)NN * DD];
__device__ float g_hB[(size_t)NN * DD];
__device__ float g_hlin[(size_t)NN * DD];
__device__ float g_asrc[NN * HH];
__device__ float g_adst[NN * HH];
__device__ int   g_deg[NN];
__device__ int   g_rowptr[NN + 1];
__device__ int   g_cursor[NN];
__device__ int   g_col[EE];
__device__ int   g_bsums[128];
__device__ float g_gcnt[GG];

__device__ __forceinline__ float lrelu(float x) { return x > 0.f ? x : NEG * x; }

// ---------------- init / CSR build ----------------
__global__ void k_zero(float* __restrict__ gout) {
    int i = blockIdx.x * blockDim.x + threadIdx.x;
    if (i < NN) g_deg[i] = 0;
    if (i < GG) g_gcnt[i] = 0.f;
    if (i < GG * DD) gout[i] = 0.f;
}

__global__ void k_count(const int* __restrict__ ei) {
    int e = blockIdx.x * blockDim.x + threadIdx.x;
    if (e < EE) atomicAdd(&g_deg[ei[EE + e]], 1);
}

__global__ void k_scan_block() {
    __shared__ int s[1024];
    int i = blockIdx.x * 1024 + threadIdx.x;
    int v = (i < NN) ? g_deg[i] : 0;
    s[threadIdx.x] = v;
    __syncthreads();
    for (int off = 1; off < 1024; off <<= 1) {
        int t = (threadIdx.x >= off) ? s[threadIdx.x - off] : 0;
        __syncthreads();
        s[threadIdx.x] += t;
        __syncthreads();
    }
    if (i < NN) g_rowptr[i] = s[threadIdx.x] - v;   // exclusive within block
    if (threadIdx.x == 1023) g_bsums[blockIdx.x] = s[1023];
}

__global__ void k_scan_bsums() {
    __shared__ int s[128];
    int t = threadIdx.x;
    int v = (t < NB1) ? g_bsums[t] : 0;
    s[t] = v;
    __syncthreads();
    for (int off = 1; off < 128; off <<= 1) {
        int u = (t >= off) ? s[t - off] : 0;
        __syncthreads();
        s[t] += u;
        __syncthreads();
    }
    if (t < NB1) g_bsums[t] = s[t] - v;             // exclusive block bases
}

__global__ void k_scan_add() {
    int i = blockIdx.x * blockDim.x + threadIdx.x;
    if (i < NN) {
        int v = g_rowptr[i] + g_bsums[i >> 10];
        g_rowptr[i] = v;
        g_cursor[i] = v;
    }
    if (i == 0) g_rowptr[NN] = EE;
}

__global__ void k_fill(const int* __restrict__ ei) {
    int e = blockIdx.x * blockDim.x + threadIdx.x;
    if (e < EE) {
        int src = ei[e];
        int dst = ei[EE + e];
        int pos = atomicAdd(&g_cursor[dst], 1);
        g_col[pos] = src;
    }
}

// ---------------- GEMMs ----------------
// layer 0: [NN,7] @ [7,128]
__global__ __launch_bounds__(128) void k_gemm0(const float* __restrict__ x,
                                               const float* __restrict__ W,
                                               float* __restrict__ out) {
    __shared__ float Ws[7 * 128];
    __shared__ float xs[8 * 7];
    int t = threadIdx.x;
    for (int i = t; i < 7 * 128; i += 128) Ws[i] = W[i];
    int base = blockIdx.x * 8;
    for (int i = t; i < 8 * 7; i += 128) {
        int nn = base + i / 7;
        xs[i] = (nn < NN) ? x[nn * 7 + (i % 7)] : 0.f;
    }
    __syncthreads();
    for (int j = 0; j < 8; j++) {
        int n = base + j;
        if (n < NN) {
            float s = 0.f;
#pragma unroll
            for (int k = 0; k < 7; k++) s = fmaf(xs[j * 7 + k], Ws[k * 128 + t], s);
            out[(size_t)n * DD + t] = s;
        }
    }
}

// layers 1-3: [NN,128] @ [128,128], BM=64 BN=128 BK=16, 256 thr, 4x8 per thread
__global__ __launch_bounds__(256) void k_gemm(const float* __restrict__ A,
                                              const float* __restrict__ B,
                                              float* __restrict__ Cout) {
    __shared__ float As[16][68];
    __shared__ float Bs[16][128];
    int tx = threadIdx.x & 15, ty = threadIdx.x >> 4;
    int row0 = blockIdx.x * 64;
    float acc[4][8];
#pragma unroll
    for (int i = 0; i < 4; i++)
#pragma unroll
        for (int j = 0; j < 8; j++) acc[i][j] = 0.f;
    int ar = threadIdx.x >> 2;
    int ak = (threadIdx.x & 3) * 4;
    for (int k0 = 0; k0 < 128; k0 += 16) {
        float4 av = make_float4(0.f, 0.f, 0.f, 0.f);
        if (row0 + ar < NN) av = *(const float4*)&A[(size_t)(row0 + ar) * DD + k0 + ak];
        As[ak + 0][ar] = av.x;
        As[ak + 1][ar] = av.y;
        As[ak + 2][ar] = av.z;
        As[ak + 3][ar] = av.w;
#pragma unroll
        for (int j = 0; j < 2; j++) {
            int t = threadIdx.x * 2 + j;
            int br = t >> 5;
            int bc = (t & 31) * 4;
            float4 bv = *(const float4*)&B[(k0 + br) * DD + bc];
            Bs[br][bc + 0] = bv.x;
            Bs[br][bc + 1] = bv.y;
            Bs[br][bc + 2] = bv.z;
            Bs[br][bc + 3] = bv.w;
        }
        __syncthreads();
#pragma unroll
        for (int kk = 0; kk < 16; kk++) {
            float a[4], b[8];
#pragma unroll
            for (int i = 0; i < 4; i++) a[i] = As[kk][ty * 4 + i];
#pragma unroll
            for (int j = 0; j < 8; j++) b[j] = Bs[kk][tx * 8 + j];
#pragma unroll
            for (int i = 0; i < 4; i++)
#pragma unroll
                for (int j = 0; j < 8; j++) acc[i][j] = fmaf(a[i], b[j], acc[i][j]);
        }
        __syncthreads();
    }
#pragma unroll
    for (int i = 0; i < 4; i++) {
        int r = row0 + ty * 4 + i;
        if (r < NN) {
            float4 v0 = make_float4(acc[i][0], acc[i][1], acc[i][2], acc[i][3]);
            float4 v1 = make_float4(acc[i][4], acc[i][5], acc[i][6], acc[i][7]);
            *(float4*)&Cout[(size_t)r * DD + tx * 8] = v0;
            *(float4*)&Cout[(size_t)r * DD + tx * 8 + 4] = v1;
        }
    }
}

// ---------------- attention coefficients: alpha_src/alpha_dst [NN,4] ----------------
__global__ __launch_bounds__(256) void k_alpha(const float* __restrict__ hlin,
                                               const float* __restrict__ aw_s,
                                               const float* __restrict__ aw_d) {
    int w = (blockIdx.x * blockDim.x + threadIdx.x) >> 5;
    if (w >= NN) return;
    int lane = threadIdx.x & 31;
    float4 hv = *(const float4*)&hlin[(size_t)w * DD + lane * 4];
    float4 ws = *(const float4*)&aw_s[lane * 4];
    float4 wd = *(const float4*)&aw_d[lane * 4];
    float ds = hv.x * ws.x + hv.y * ws.y + hv.z * ws.z + hv.w * ws.w;
    float dd = hv.x * wd.x + hv.y * wd.y + hv.z * wd.z + hv.w * wd.w;
#pragma unroll
    for (int o = 4; o >= 1; o >>= 1) {
        ds += __shfl_xor_sync(0xffffffffu, ds, o);
        dd += __shfl_xor_sync(0xffffffffu, dd, o);
    }
    if ((lane & 7) == 0) {
        g_asrc[w * 4 + (lane >> 3)] = ds;
        g_adst[w * 4 + (lane >> 3)] = dd;
    }
}

// ---------------- fused GAT layer: softmax attention + aggregate + bias + LN + ELU + residual
// one warp per destination node; self-loop handled inline
__global__ __launch_bounds__(256) void k_gat(const float* __restrict__ hlin,
                                             const float* __restrict__ hprev,
                                             const float* __restrict__ bias,
                                             const float* __restrict__ gam,
                                             const float* __restrict__ bet,
                                             float* __restrict__ outp, int residual) {
    int n = (blockIdx.x * blockDim.x + threadIdx.x) >> 5;
    if (n >= NN) return;
    int lane = threadIdx.x & 31;
    int hd = lane >> 3;
    int rs = g_rowptr[n], re = g_rowptr[n + 1];
    float4 ad4 = *(const float4*)&g_adst[n * 4];
    float4 as4 = *(const float4*)&g_asrc[n * 4];
    float ad[4] = {ad4.x, ad4.y, ad4.z, ad4.w};
    float sl[4];
    sl[0] = lrelu(as4.x + ad[0]);
    sl[1] = lrelu(as4.y + ad[1]);
    sl[2] = lrelu(as4.z + ad[2]);
    sl[3] = lrelu(as4.w + ad[3]);
    float mx[4] = {sl[0], sl[1], sl[2], sl[3]};
    // pass 1: segment max (lane-parallel over edges)
    for (int i = rs + lane; i < re; i += 32) {
        int s = __ldg(&g_col[i]);
        float4 a = *(const float4*)&g_asrc[s * 4];
        mx[0] = fmaxf(mx[0], lrelu(a.x + ad[0]));
        mx[1] = fmaxf(mx[1], lrelu(a.y + ad[1]));
        mx[2] = fmaxf(mx[2], lrelu(a.z + ad[2]));
        mx[3] = fmaxf(mx[3], lrelu(a.w + ad[3]));
    }
#pragma unroll
    for (int o = 16; o >= 1; o >>= 1) {
        mx[0] = fmaxf(mx[0], __shfl_xor_sync(0xffffffffu, mx[0], o));
        mx[1] = fmaxf(mx[1], __shfl_xor_sync(0xffffffffu, mx[1], o));
        mx[2] = fmaxf(mx[2], __shfl_xor_sync(0xffffffffu, mx[2], o));
        mx[3] = fmaxf(mx[3], __shfl_xor_sync(0xffffffffu, mx[3], o));
    }
    // pass 2: exp-sum
    float z[4];
    z[0] = __expf(sl[0] - mx[0]);
    z[1] = __expf(sl[1] - mx[1]);
    z[2] = __expf(sl[2] - mx[2]);
    z[3] = __expf(sl[3] - mx[3]);
    // self-loop term counted once: zero it on all lanes but 0
    if (lane != 0) { z[0] = 0.f; z[1] = 0.f; z[2] = 0.f; z[3] = 0.f; }
    for (int i = rs + lane; i < re; i += 32) {
        int s = __ldg(&g_col[i]);
        float4 a = *(const float4*)&g_asrc[s * 4];
        z[0] += __expf(lrelu(a.x + ad[0]) - mx[0]);
        z[1] += __expf(lrelu(a.y + ad[1]) - mx[1]);
        z[2] += __expf(lrelu(a.z + ad[2]) - mx[2]);
        z[3] += __expf(lrelu(a.w + ad[3]) - mx[3]);
    }
#pragma unroll
    for (int o = 16; o >= 1; o >>= 1) {
        z[0] += __shfl_xor_sync(0xffffffffu, z[0], o);
        z[1] += __shfl_xor_sync(0xffffffffu, z[1], o);
        z[2] += __shfl_xor_sync(0xffffffffu, z[2], o);
        z[3] += __shfl_xor_sync(0xffffffffu, z[3], o);
    }
    // pass 3: weighted aggregate, lanes channel-parallel (4 ch each)
    float mxh = mx[hd], adh = ad[hd];
    float invz = 1.f / (z[hd] + 1e-16f);
    float wslf = __expf(sl[hd] - mxh) * invz;
    float4 hv = *(const float4*)&hlin[(size_t)n * DD + lane * 4];
    float a0 = hv.x * wslf, a1 = hv.y * wslf, a2 = hv.z * wslf, a3 = hv.w * wslf;
#pragma unroll 2
    for (int i = rs; i < re; i++) {
        int s = __ldg(&g_col[i]);
        float asv = __ldg(&g_asrc[s * 4 + hd]);
        float wgt = __expf(lrelu(asv + adh) - mxh) * invz;
        float4 hs = *(const float4*)&hlin[(size_t)s * DD + lane * 4];
        a0 = fmaf(hs.x, wgt, a0);
        a1 = fmaf(hs.y, wgt, a1);
        a2 = fmaf(hs.z, wgt, a2);
        a3 = fmaf(hs.w, wgt, a3);
    }
    // epilogue: bias + LayerNorm + ELU + residual, all in-register
    float4 bv = *(const float4*)&bias[lane * 4];
    a0 += bv.x; a1 += bv.y; a2 += bv.z; a3 += bv.w;
    float sm = a0 + a1 + a2 + a3;
#pragma unroll
    for (int o = 16; o >= 1; o >>= 1) sm += __shfl_xor_sync(0xffffffffu, sm, o);
    float mean = sm * (1.f / DD);
    float d0 = a0 - mean, d1 = a1 - mean, d2 = a2 - mean, d3 = a3 - mean;
    float sq = d0 * d0 + d1 * d1 + d2 * d2 + d3 * d3;
#pragma unroll
    for (int o = 16; o >= 1; o >>= 1) sq += __shfl_xor_sync(0xffffffffu, sq, o);
    float rstd = rsqrtf(sq * (1.f / DD) + 1e-5f);
    float4 gv = *(const float4*)&gam[lane * 4];
    float4 bev = *(const float4*)&bet[lane * 4];
    float v0 = d0 * rstd * gv.x + bev.x;
    float v1 = d1 * rstd * gv.y + bev.y;
    float v2 = d2 * rstd * gv.z + bev.z;
    float v3 = d3 * rstd * gv.w + bev.w;
    v0 = v0 > 0.f ? v0 : __expf(v0) - 1.f;
    v1 = v1 > 0.f ? v1 : __expf(v1) - 1.f;
    v2 = v2 > 0.f ? v2 : __expf(v2) - 1.f;
    v3 = v3 > 0.f ? v3 : __expf(v3) - 1.f;
    if (residual) {
        float4 pv = *(const float4*)&hprev[(size_t)n * DD + lane * 4];
        v0 += pv.x; v1 += pv.y; v2 += pv.z; v3 += pv.w;
    }
    *(float4*)&outp[(size_t)n * DD + lane * 4] = make_float4(v0, v1, v2, v3);
}

// ---------------- graph pooling ----------------
__global__ void k_cnt(const int* __restrict__ batch) {
    int i = blockIdx.x * blockDim.x + threadIdx.x;
    if (i < NN) atomicAdd(&g_gcnt[batch[i]], 1.f);
}

__global__ __launch_bounds__(128) void k_pool(const float* __restrict__ ne,
                                              const int* __restrict__ batch,
                                              float* __restrict__ gout) {
    int base = blockIdx.x * 128;
    if (base >= NN) return;
    int d = threadIdx.x;
    int end = base + 128;
    if (end > NN) end = NN;
    float acc = 0.f;
    int cg = __ldg(&batch[base]);
    for (int n = base; n < end; n++) {
        int gidx = __ldg(&batch[n]);
        if (gidx != cg) {
            atomicAdd(&gout[cg * DD + d], acc);
            acc = 0.f;
            cg = gidx;
        }
        acc += ne[(size_t)n * DD + d];
    }
    atomicAdd(&gout[cg * DD + d], acc);
}

__global__ void k_final(float* __restrict__ gout) {
    int i = blockIdx.x * blockDim.x + threadIdx.x;
    if (i < GG * DD) gout[i] /= fmaxf(g_gcnt[i >> 7], 1.f);
}

// ---------------- host launch ----------------
extern "C" void kernel_launch(void* const* d_in, const int* in_sizes, int n_in,
                              void* d_out, int out_size) {
    const float* x    = (const float*)d_in[0];
    const int*   ei   = (const int*)d_in[1];
    const int*   batch= (const int*)d_in[2];
    const float* W0   = (const float*)d_in[3];
    const float* as0  = (const float*)d_in[4];
    const float* ad0  = (const float*)d_in[5];
    const float* b0   = (const float*)d_in[6];
    const float* Ws   = (const float*)d_in[7];
    const float* asr  = (const float*)d_in[8];
    const float* ads  = (const float*)d_in[9];
    const float* bs   = (const float*)d_in[10];
    const float* lng  = (const float*)d_in[11];
    const float* lnb  = (const float*)d_in[12];
    float* out  = (float*)d_out;
    float* gout = out + (size_t)NN * DD;

    float *hA, *hB, *hlin;
    cudaGetSymbolAddress((void**)&hA, g_hA);
    cudaGetSymbolAddress((void**)&hB, g_hB);
    cudaGetSymbolAddress((void**)&hlin, g_hlin);

    // CSR build (once per launch; shared by all 4 layers)
    k_zero<<<(NN + 255) / 256, 256>>>(gout);
    k_count<<<(EE + 255) / 256, 256>>>(ei);
    k_scan_block<<<NB1, 1024>>>();
    k_scan_bsums<<<1, 128>>>();
    k_scan_add<<<(NN + 255) / 256, 256>>>();
    k_fill<<<(EE + 255) / 256, 256>>>(ei);

    // layer 0
    k_gemm0<<<(NN + 7) / 8, 128>>>(x, W0, hlin);
    k_alpha<<<(NN * 32 + 255) / 256, 256>>>(hlin, as0, ad0);
    k_gat<<<(NN * 32 + 255) / 256, 256>>>(hlin, nullptr, b0, lng, lnb, hA, 0);

    // layers 1..3
    const float* cur = hA;
    for (int l = 1; l < 4; l++) {
        float* nxt = (l == 3) ? out : ((l & 1) ? hB : hA);
        k_gemm<<<(NN + 63) / 64, 256>>>(cur, Ws + (size_t)(l - 1) * DD * DD, hlin);
        k_alpha<<<(NN * 32 + 255) / 256, 256>>>(hlin, asr + (l - 1) * DD, ads + (l - 1) * DD);
        k_gat<<<(NN * 32 + 255) / 256, 256>>>(hlin, cur, bs + (l - 1) * DD,
                                              lng + l * DD, lnb + l * DD, nxt, 1);
        cur = nxt;
    }

    // graph mean pooling
    k_cnt<<<(NN + 255) / 256, 256>>>(batch);
    k_pool<<<(NN + 127) / 128, 128>>>(out, batch, gout);
    k_final<<<(GG * DD + 255) / 256, 256>>>(gout);
}

// round 2
// speedup vs baseline: 1.1020x; 1.1020x over previous
#include <cuda_runtime.h>

#define NN 100000
#define EE 1600000
#define HH 4
#define CC 32
#define DD 128
#define GG 64
#define NEG 0.2f
#define NB1 ((NN + 1023) / 1024)

// ---------------- device scratch (no runtime allocation allowed) ----------------
__device__ float g_hA[(size_t)NN * DD];
__device__ float g_hB[(size_t)NN * DD];
__device__ float g_hlin[(size_t)NN * DD];
__device__ float g_asrc[NN * HH];
__device__ float g_adst[NN * HH];
__device__ int   g_deg[NN];
__device__ int   g_rowptr[NN + 1];
__device__ int   g_cursor[NN];
__device__ int   g_col[EE];
__device__ int   g_bsums[128];
__device__ float g_gcnt[GG];

__device__ __forceinline__ float lrelu(float x) { return x > 0.f ? x : NEG * x; }

// ---------------- init / CSR build ----------------
__global__ void k_zero(float* __restrict__ gout) {
    int i = blockIdx.x * blockDim.x + threadIdx.x;
    if (i < NN) g_deg[i] = 0;
    if (i < GG) g_gcnt[i] = 0.f;
    if (i < GG * DD) gout[i] = 0.f;
}

__global__ void k_count(const int* __restrict__ ei) {
    int e = blockIdx.x * blockDim.x + threadIdx.x;
    if (e < EE) atomicAdd(&g_deg[ei[EE + e]], 1);
}

__global__ void k_scan_block() {
    __shared__ int s[1024];
    int i = blockIdx.x * 1024 + threadIdx.x;
    int v = (i < NN) ? g_deg[i] : 0;
    s[threadIdx.x] = v;
    __syncthreads();
    for (int off = 1; off < 1024; off <<= 1) {
        int t = (threadIdx.x >= off) ? s[threadIdx.x - off] : 0;
        __syncthreads();
        s[threadIdx.x] += t;
        __syncthreads();
    }
    if (i < NN) g_rowptr[i] = s[threadIdx.x] - v;
    if (threadIdx.x == 1023) g_bsums[blockIdx.x] = s[1023];
}

__global__ void k_scan_bsums() {
    __shared__ int s[128];
    int t = threadIdx.x;
    int v = (t < NB1) ? g_bsums[t] : 0;
    s[t] = v;
    __syncthreads();
    for (int off = 1; off < 128; off <<= 1) {
        int u = (t >= off) ? s[t - off] : 0;
        __syncthreads();
        s[t] += u;
        __syncthreads();
    }
    if (t < NB1) g_bsums[t] = s[t] - v;
}

__global__ void k_scan_add() {
    int i = blockIdx.x * blockDim.x + threadIdx.x;
    if (i < NN) {
        int v = g_rowptr[i] + g_bsums[i >> 10];
        g_rowptr[i] = v;
        g_cursor[i] = v;
    }
    if (i == 0) g_rowptr[NN] = EE;
}

__global__ void k_fill(const int* __restrict__ ei) {
    int e = blockIdx.x * blockDim.x + threadIdx.x;
    if (e < EE) {
        int src = ei[e];
        int dst = ei[EE + e];
        int pos = atomicAdd(&g_cursor[dst], 1);
        g_col[pos] = src;
    }
}

// ---------------- GEMMs ----------------
// layer 0: [NN,7] @ [7,128]
__global__ __launch_bounds__(128) void k_gemm0(const float* __restrict__ x,
                                               const float* __restrict__ W,
                                               float* __restrict__ out) {
    __shared__ float Ws[7 * 128];
    __shared__ float xs[8 * 7];
    int t = threadIdx.x;
    for (int i = t; i < 7 * 128; i += 128) Ws[i] = W[i];
    int base = blockIdx.x * 8;
    for (int i = t; i < 8 * 7; i += 128) {
        int nn = base + i / 7;
        xs[i] = (nn < NN) ? x[nn * 7 + (i % 7)] : 0.f;
    }
    __syncthreads();
    for (int j = 0; j < 8; j++) {
        int n = base + j;
        if (n < NN) {
            float s = 0.f;
#pragma unroll
            for (int k = 0; k < 7; k++) s = fmaf(xs[j * 7 + k], Ws[k * 128 + t], s);
            out[(size_t)n * DD + t] = s;
        }
    }
}

// layers 1-3: [NN,128] @ [128,128]
// BM=128 BN=128 BK=16, 256 threads, 8x8 per thread, double-buffered smem
__global__ __launch_bounds__(256) void k_gemm(const float* __restrict__ A,
                                              const float* __restrict__ B,
                                              float* __restrict__ Cout) {
    __shared__ float As[2][16][132];   // k-major, +4 pad
    __shared__ float Bs[2][16][128];
    const int tid = threadIdx.x;
    const int tx = tid & 15;           // n tile: cols tx*8..tx*8+7
    const int ty = tid >> 4;           // m tile: rows ty*8..ty*8+7
    const int row0 = blockIdx.x * 128;

    // A load mapping: idx in [0,512): a_row = idx>>2, a_k4 = (idx&3)*4
    const int a_row0 = tid >> 2;               // idx = tid
    const int a_row1 = (tid + 256) >> 2;       // idx = tid+256
    const int a_k = (tid & 3) * 4;             // same for both (idx&3 identical)
    // B load mapping: b_row = idx>>5, b_c = (idx&31)*4
    const int b_row0 = tid >> 5;
    const int b_row1 = (tid + 256) >> 5;
    const int b_c = (tid & 31) * 4;

    const int gr0 = min(row0 + a_row0, NN - 1);
    const int gr1 = min(row0 + a_row1, NN - 1);

    float acc[8][8];
#pragma unroll
    for (int i = 0; i < 8; i++)
#pragma unroll
        for (int j = 0; j < 8; j++) acc[i][j] = 0.f;

    // prefetch tile 0
    float4 rA0 = *(const float4*)&A[(size_t)gr0 * DD + a_k];
    float4 rA1 = *(const float4*)&A[(size_t)gr1 * DD + a_k];
    float4 rB0 = *(const float4*)&B[b_row0 * DD + b_c];
    float4 rB1 = *(const float4*)&B[b_row1 * DD + b_c];
    {
        As[0][a_k + 0][a_row0] = rA0.x; As[0][a_k + 1][a_row0] = rA0.y;
        As[0][a_k + 2][a_row0] = rA0.z; As[0][a_k + 3][a_row0] = rA0.w;
        As[0][a_k + 0][a_row1] = rA1.x; As[0][a_k + 1][a_row1] = rA1.y;
        As[0][a_k + 2][a_row1] = rA1.z; As[0][a_k + 3][a_row1] = rA1.w;
        *(float4*)&Bs[0][b_row0][b_c] = rB0;
        *(float4*)&Bs[0][b_row1][b_c] = rB1;
    }
    __syncthreads();

#pragma unroll
    for (int t = 0; t < 8; t++) {
        const int cur = t & 1;
        if (t < 7) {
            const int k0 = (t + 1) * 16;
            rA0 = *(const float4*)&A[(size_t)gr0 * DD + k0 + a_k];
            rA1 = *(const float4*)&A[(size_t)gr1 * DD + k0 + a_k];
            rB0 = *(const float4*)&B[(k0 + b_row0) * DD + b_c];
            rB1 = *(const float4*)&B[(k0 + b_row1) * DD + b_c];
        }
#pragma unroll
        for (int kk = 0; kk < 16; kk++) {
            float4 a0 = *(const float4*)&As[cur][kk][ty * 8];
            float4 a1 = *(const float4*)&As[cur][kk][ty * 8 + 4];
            float4 b0 = *(const float4*)&Bs[cur][kk][tx * 8];
            float4 b1 = *(const float4*)&Bs[cur][kk][tx * 8 + 4];
            float av[8] = {a0.x, a0.y, a0.z, a0.w, a1.x, a1.y, a1.z, a1.w};
            float bv[8] = {b0.x, b0.y, b0.z, b0.w, b1.x, b1.y, b1.z, b1.w};
#pragma unroll
            for (int i = 0; i < 8; i++)
#pragma unroll
                for (int j = 0; j < 8; j++) acc[i][j] = fmaf(av[i], bv[j], acc[i][j]);
        }
        if (t < 7) {
            const int nxt = cur ^ 1;
            As[nxt][a_k + 0][a_row0] = rA0.x; As[nxt][a_k + 1][a_row0] = rA0.y;
            As[nxt][a_k + 2][a_row0] = rA0.z; As[nxt][a_k + 3][a_row0] = rA0.w;
            As[nxt][a_k + 0][a_row1] = rA1.x; As[nxt][a_k + 1][a_row1] = rA1.y;
            As[nxt][a_k + 2][a_row1] = rA1.z; As[nxt][a_k + 3][a_row1] = rA1.w;
            *(float4*)&Bs[nxt][b_row0][b_c] = rB0;
            *(float4*)&Bs[nxt][b_row1][b_c] = rB1;
        }
        __syncthreads();
    }

#pragma unroll
    for (int i = 0; i < 8; i++) {
        int r = row0 + ty * 8 + i;
        if (r < NN) {
            float4 v0 = make_float4(acc[i][0], acc[i][1], acc[i][2], acc[i][3]);
            float4 v1 = make_float4(acc[i][4], acc[i][5], acc[i][6], acc[i][7]);
            *(float4*)&Cout[(size_t)r * DD + tx * 8] = v0;
            *(float4*)&Cout[(size_t)r * DD + tx * 8 + 4] = v1;
        }
    }
}

// ---------------- attention coefficients: alpha_src/alpha_dst [NN,4] ----------------
__global__ __launch_bounds__(256) void k_alpha(const float* __restrict__ hlin,
                                               const float* __restrict__ aw_s,
                                               const float* __restrict__ aw_d) {
    int w = (blockIdx.x * blockDim.x + threadIdx.x) >> 5;
    if (w >= NN) return;
    int lane = threadIdx.x & 31;
    float4 hv = *(const float4*)&hlin[(size_t)w * DD + lane * 4];
    float4 ws = *(const float4*)&aw_s[lane * 4];
    float4 wd = *(const float4*)&aw_d[lane * 4];
    float ds = hv.x * ws.x + hv.y * ws.y + hv.z * ws.z + hv.w * ws.w;
    float dd = hv.x * wd.x + hv.y * wd.y + hv.z * wd.z + hv.w * wd.w;
#pragma unroll
    for (int o = 4; o >= 1; o >>= 1) {
        ds += __shfl_xor_sync(0xffffffffu, ds, o);
        dd += __shfl_xor_sync(0xffffffffu, dd, o);
    }
    if ((lane & 7) == 0) {
        g_asrc[w * 4 + (lane >> 3)] = ds;
        g_adst[w * 4 + (lane >> 3)] = dd;
    }
}

// ---------------- fused GAT layer: SINGLE-PASS softmax attention + aggregate
// + bias + LN + ELU + residual. One warp per destination node.
// Max-subtraction dropped (cancels exactly in alpha = e/z; logits are O(1)).
// Normalization deferred: accumulate unnormalized sum and z, divide at end.
__global__ __launch_bounds__(256) void k_gat(const float* __restrict__ hlin,
                                             const float* __restrict__ hprev,
                                             const float* __restrict__ bias,
                                             const float* __restrict__ gam,
                                             const float* __restrict__ bet,
                                             float* __restrict__ outp, int residual) {
    __shared__ float ws_sm[8][32][4];
    __shared__ int   sc_sm[8][32];
    int n = (blockIdx.x * blockDim.x + threadIdx.x) >> 5;
    if (n >= NN) return;
    int lane = threadIdx.x & 31;
    int wslot = (threadIdx.x >> 5) & 7;
    int hd = lane >> 3;
    int rs = g_rowptr[n], re = g_rowptr[n + 1];

    float4 ad4 = *(const float4*)&g_adst[n * 4];
    float4 as4 = *(const float4*)&g_asrc[n * 4];
    float ad0 = ad4.x, ad1 = ad4.y, ad2 = ad4.z, ad3 = ad4.w;

    // self-loop weights
    float w0 = __expf(lrelu(as4.x + ad0));
    float w1 = __expf(lrelu(as4.y + ad1));
    float w2 = __expf(lrelu(as4.z + ad2));
    float w3 = __expf(lrelu(as4.w + ad3));
    // z accumulators (self-loop counted once, on lane 0 only)
    float z0 = (lane == 0) ? w0 : 0.f;
    float z1 = (lane == 0) ? w1 : 0.f;
    float z2 = (lane == 0) ? w2 : 0.f;
    float z3 = (lane == 0) ? w3 : 0.f;

    // unnormalized self contribution (per-lane channels)
    float wslf = (hd == 0) ? w0 : (hd == 1) ? w1 : (hd == 2) ? w2 : w3;
    float4 hv = *(const float4*)&hlin[(size_t)n * DD + lane * 4];
    float a0 = hv.x * wslf, a1 = hv.y * wslf, a2 = hv.z * wslf, a3 = hv.w * wslf;

    for (int c = rs; c < re; c += 32) {
        int cnt = re - c;
        if (cnt > 32) cnt = 32;
        if (lane < cnt) {
            int s = __ldg(&g_col[c + lane]);
            float4 a = *(const float4*)&g_asrc[s * 4];
            float e0 = __expf(lrelu(a.x + ad0));
            float e1 = __expf(lrelu(a.y + ad1));
            float e2 = __expf(lrelu(a.z + ad2));
            float e3 = __expf(lrelu(a.w + ad3));
            z0 += e0; z1 += e1; z2 += e2; z3 += e3;
            sc_sm[wslot][lane] = s;
            ws_sm[wslot][lane][0] = e0;
            ws_sm[wslot][lane][1] = e1;
            ws_sm[wslot][lane][2] = e2;
            ws_sm[wslot][lane][3] = e3;
        }
        __syncwarp();
#pragma unroll 2
        for (int j = 0; j < cnt; j++) {
            int sj = sc_sm[wslot][j];
            float wj = ws_sm[wslot][j][hd];
            float4 hs = *(const float4*)&hlin[(size_t)sj * DD + lane * 4];
            a0 = fmaf(hs.x, wj, a0);
            a1 = fmaf(hs.y, wj, a1);
            a2 = fmaf(hs.z, wj, a2);
            a3 = fmaf(hs.w, wj, a3);
        }
        __syncwarp();
    }
    // total z per head = sum over all lanes
#pragma unroll
    for (int o = 16; o >= 1; o >>= 1) {
        z0 += __shfl_xor_sync(0xffffffffu, z0, o);
        z1 += __shfl_xor_sync(0xffffffffu, z1, o);
        z2 += __shfl_xor_sync(0xffffffffu, z2, o);
        z3 += __shfl_xor_sync(0xffffffffu, z3, o);
    }
    float zh = (hd == 0) ? z0 : (hd == 1) ? z1 : (hd == 2) ? z2 : z3;
    float invz = 1.f / (zh + 1e-16f);
    a0 *= invz; a1 *= invz; a2 *= invz; a3 *= invz;

    // epilogue: bias + LayerNorm + ELU + residual, all in-register
    float4 bv = *(const float4*)&bias[lane * 4];
    a0 += bv.x; a1 += bv.y; a2 += bv.z; a3 += bv.w;
    float sm = a0 + a1 + a2 + a3;
#pragma unroll
    for (int o = 16; o >= 1; o >>= 1) sm += __shfl_xor_sync(0xffffffffu, sm, o);
    float mean = sm * (1.f / DD);
    float d0 = a0 - mean, d1 = a1 - mean, d2 = a2 - mean, d3 = a3 - mean;
    float sq = d0 * d0 + d1 * d1 + d2 * d2 + d3 * d3;
#pragma unroll
    for (int o = 16; o >= 1; o >>= 1) sq += __shfl_xor_sync(0xffffffffu, sq, o);
    float rstd = rsqrtf(sq * (1.f / DD) + 1e-5f);
    float4 gv = *(const float4*)&gam[lane * 4];
    float4 bev = *(const float4*)&bet[lane * 4];
    float v0 = d0 * rstd * gv.x + bev.x;
    float v1 = d1 * rstd * gv.y + bev.y;
    float v2 = d2 * rstd * gv.z + bev.z;
    float v3 = d3 * rstd * gv.w + bev.w;
    v0 = v0 > 0.f ? v0 : __expf(v0) - 1.f;
    v1 = v1 > 0.f ? v1 : __expf(v1) - 1.f;
    v2 = v2 > 0.f ? v2 : __expf(v2) - 1.f;
    v3 = v3 > 0.f ? v3 : __expf(v3) - 1.f;
    if (residual) {
        float4 pv = *(const float4*)&hprev[(size_t)n * DD + lane * 4];
        v0 += pv.x; v1 += pv.y; v2 += pv.z; v3 += pv.w;
    }
    *(float4*)&outp[(size_t)n * DD + lane * 4] = make_float4(v0, v1, v2, v3);
}

// ---------------- graph pooling ----------------
__global__ void k_cnt(const int* __restrict__ batch) {
    int i = blockIdx.x * blockDim.x + threadIdx.x;
    if (i < NN) atomicAdd(&g_gcnt[batch[i]], 1.f);
}

__global__ __launch_bounds__(128) void k_pool(const float* __restrict__ ne,
                                              const int* __restrict__ batch,
                                              float* __restrict__ gout) {
    int base = blockIdx.x * 128;
    if (base >= NN) return;
    int d = threadIdx.x;
    int end = base + 128;
    if (end > NN) end = NN;
    float acc = 0.f;
    int cg = __ldg(&batch[base]);
    for (int n = base; n < end; n++) {
        int gidx = __ldg(&batch[n]);
        if (gidx != cg) {
            atomicAdd(&gout[cg * DD + d], acc);
            acc = 0.f;
            cg = gidx;
        }
        acc += ne[(size_t)n * DD + d];
    }
    atomicAdd(&gout[cg * DD + d], acc);
}

__global__ void k_final(float* __restrict__ gout) {
    int i = blockIdx.x * blockDim.x + threadIdx.x;
    if (i < GG * DD) gout[i] /= fmaxf(g_gcnt[i >> 7], 1.f);
}

// ---------------- host launch ----------------
extern "C" void kernel_launch(void* const* d_in, const int* in_sizes, int n_in,
                              void* d_out, int out_size) {
    const float* x    = (const float*)d_in[0];
    const int*   ei   = (const int*)d_in[1];
    const int*   batch= (const int*)d_in[2];
    const float* W0   = (const float*)d_in[3];
    const float* as0  = (const float*)d_in[4];
    const float* ad0  = (const float*)d_in[5];
    const float* b0   = (const float*)d_in[6];
    const float* Ws   = (const float*)d_in[7];
    const float* asr  = (const float*)d_in[8];
    const float* ads  = (const float*)d_in[9];
    const float* bs   = (const float*)d_in[10];
    const float* lng  = (const float*)d_in[11];
    const float* lnb  = (const float*)d_in[12];
    float* out  = (float*)d_out;
    float* gout = out + (size_t)NN * DD;

    float *hA, *hB, *hlin;
    cudaGetSymbolAddress((void**)&hA, g_hA);
    cudaGetSymbolAddress((void**)&hB, g_hB);
    cudaGetSymbolAddress((void**)&hlin, g_hlin);

    // CSR build (once per launch; shared by all 4 layers)
    k_zero<<<(NN + 255) / 256, 256>>>(gout);
    k_count<<<(EE + 255) / 256, 256>>>(ei);
    k_scan_block<<<NB1, 1024>>>();
    k_scan_bsums<<<1, 128>>>();
    k_scan_add<<<(NN + 255) / 256, 256>>>();
    k_fill<<<(EE + 255) / 256, 256>>>(ei);

    // layer 0
    k_gemm0<<<(NN + 7) / 8, 128>>>(x, W0, hlin);
    k_alpha<<<(NN * 32 + 255) / 256, 256>>>(hlin, as0, ad0);
    k_gat<<<(NN * 32 + 255) / 256, 256>>>(hlin, nullptr, b0, lng, lnb, hA, 0);

    // layers 1..3
    const float* cur = hA;
    for (int l = 1; l < 4; l++) {
        float* nxt = (l == 3) ? out : ((l & 1) ? hB : hA);
        k_gemm<<<(NN + 127) / 128, 256>>>(cur, Ws + (size_t)(l - 1) * DD * DD, hlin);
        k_alpha<<<(NN * 32 + 255) / 256, 256>>>(hlin, asr + (l - 1) * DD, ads + (l - 1) * DD);
        k_gat<<<(NN * 32 + 255) / 256, 256>>>(hlin, cur, bs + (l - 1) * DD,
                                              lng + l * DD, lnb + l * DD, nxt, 1);
        cur = nxt;
    }

    // graph mean pooling
    k_cnt<<<(NN + 255) / 256, 256>>>(batch);
    k_pool<<<(NN + 127) / 128, 128>>>(out, batch, gout);
    k_final<<<(GG * DD + 255) / 256, 256>>>(gout);
}